// round 3
// baseline (speedup 1.0000x reference)
#include <cuda_runtime.h>

// Problem constants (fixed by the dataset)
#define NNODES 50000
#define NEDGES 500000
#define NGRAPH 50
#define NPG    1000   // nodes per graph
#define NH     4      // heads

// ---------------- scratch (device globals: allocation-free) ----------------
__device__ float g_f1[(size_t)NNODES * 512];    // [N][512]: cols 0..255 fs1, 256..511 fd1
__device__ float g_h1[(size_t)NNODES * 64];     // layer-1 output  [N,64]
__device__ float g_f2[(size_t)NNODES * 1024];   // [N][1024]: 0..511 fs2, 512..1023 fd2
__device__ float g_h2[(size_t)NNODES * 128];    // layer-2 output  [N,128]
__device__ int   g_deg[NNODES];
__device__ int   g_off[NNODES + 1];
__device__ int   g_cur[NNODES];
__device__ int   g_csr[NEDGES];                 // src node per CSR slot (grouped by dst)

// ---------------- CSR construction ----------------
__global__ void k_zero_deg() {
    int i = blockIdx.x * blockDim.x + threadIdx.x;
    if (i < NNODES) g_deg[i] = 0;
}

__global__ void k_count(const int* __restrict__ dst) {
    for (int e = blockIdx.x * blockDim.x + threadIdx.x; e < NEDGES;
         e += gridDim.x * blockDim.x)
        atomicAdd(&g_deg[dst[e]], 1);
}

// single-block exclusive scan over g_deg -> g_off (and g_cur copy)
__global__ void k_scan() {
    __shared__ int sh[1024];
    __shared__ int carry;
    int tid = threadIdx.x;
    if (tid == 0) carry = 0;
    __syncthreads();
    for (int base = 0; base < NNODES; base += 1024) {
        int i = base + tid;
        int v = (i < NNODES) ? g_deg[i] : 0;
        sh[tid] = v;
        __syncthreads();
        for (int o = 1; o < 1024; o <<= 1) {
            int t = (tid >= o) ? sh[tid - o] : 0;
            __syncthreads();
            sh[tid] += t;
            __syncthreads();
        }
        int inc = sh[tid];
        int cbase = carry;
        if (i < NNODES) {
            int exc = cbase + inc - v;
            g_off[i] = exc;
            g_cur[i] = exc;
        }
        int total = sh[1023];
        __syncthreads();
        if (tid == 0) carry = cbase + total;
        // next iteration's first __syncthreads orders this write vs. reads
    }
    __syncthreads();
    if (tid == 0) g_off[NNODES] = carry;
}

__global__ void k_scatter(const int* __restrict__ src, const int* __restrict__ dst) {
    for (int e = blockIdx.x * blockDim.x + threadIdx.x; e < NEDGES;
         e += gridDim.x * blockDim.x) {
        int pos = atomicAdd(&g_cur[dst[e]], 1);
        g_csr[pos] = src[e];
    }
}

// ---------------- fused dual GEMM + bias ----------------
// out[n, c] = A[n,:] @ (c < Mh ? Wl[:,c] : Wr[:,c-Mh]) + bias
// BM=BN=64, BK=32, 256 threads, 4x4 microtile.
// LAYER==1: A = Aparam (x), out = g_f1 ; LAYER==2: A = g_h1, out = g_f2
template <int K, int LAYER>
__launch_bounds__(256)
__global__ void gemm_bias(const float* __restrict__ Aparam,
                          const float* __restrict__ Wl, const float* __restrict__ bl,
                          const float* __restrict__ Wr, const float* __restrict__ br,
                          int Mh) {
    const float* __restrict__ A = (LAYER == 1) ? Aparam : g_h1;
    float* __restrict__ out = (LAYER == 1) ? g_f1 : g_f2;

    __shared__ float As[64][33];
    __shared__ __align__(16) float Bs[32][64];

    int tid = threadIdx.x;
    int ty = tid >> 4, tx = tid & 15;
    int r0 = blockIdx.x * 64;
    int c0 = blockIdx.y * 64;

    const float* W;
    const float* b;
    int cc0;
    if (c0 < Mh) { W = Wl; b = bl; cc0 = c0; }
    else         { W = Wr; b = br; cc0 = c0 - Mh; }

    float acc[4][4] = {};

    for (int kb = 0; kb < K; kb += 32) {
#pragma unroll
        for (int i = tid; i < 64 * 32; i += 256) {
            int row = i >> 5, k = i & 31;
            int gr = r0 + row;
            As[row][k] = (gr < NNODES) ? A[(size_t)gr * K + kb + k] : 0.f;
        }
#pragma unroll
        for (int i = tid; i < 32 * 64; i += 256) {
            int k = i >> 6, c = i & 63;
            Bs[k][c] = W[(size_t)(kb + k) * Mh + cc0 + c];
        }
        __syncthreads();
#pragma unroll
        for (int kk = 0; kk < 32; kk++) {
            float a0 = As[ty * 4 + 0][kk];
            float a1 = As[ty * 4 + 1][kk];
            float a2 = As[ty * 4 + 2][kk];
            float a3 = As[ty * 4 + 3][kk];
            float4 bv = *(const float4*)&Bs[kk][tx * 4];
            acc[0][0] = fmaf(a0, bv.x, acc[0][0]); acc[0][1] = fmaf(a0, bv.y, acc[0][1]);
            acc[0][2] = fmaf(a0, bv.z, acc[0][2]); acc[0][3] = fmaf(a0, bv.w, acc[0][3]);
            acc[1][0] = fmaf(a1, bv.x, acc[1][0]); acc[1][1] = fmaf(a1, bv.y, acc[1][1]);
            acc[1][2] = fmaf(a1, bv.z, acc[1][2]); acc[1][3] = fmaf(a1, bv.w, acc[1][3]);
            acc[2][0] = fmaf(a2, bv.x, acc[2][0]); acc[2][1] = fmaf(a2, bv.y, acc[2][1]);
            acc[2][2] = fmaf(a2, bv.z, acc[2][2]); acc[2][3] = fmaf(a2, bv.w, acc[2][3]);
            acc[3][0] = fmaf(a3, bv.x, acc[3][0]); acc[3][1] = fmaf(a3, bv.y, acc[3][1]);
            acc[3][2] = fmaf(a3, bv.z, acc[3][2]); acc[3][3] = fmaf(a3, bv.w, acc[3][3]);
        }
        __syncthreads();
    }

    float bv0 = b[cc0 + tx * 4 + 0];
    float bv1 = b[cc0 + tx * 4 + 1];
    float bv2 = b[cc0 + tx * 4 + 2];
    float bv3 = b[cc0 + tx * 4 + 3];
    int M2 = 2 * Mh;
#pragma unroll
    for (int i = 0; i < 4; i++) {
        int row = r0 + ty * 4 + i;
        if (row < NNODES) {
            float4 o;
            o.x = acc[i][0] + bv0;
            o.y = acc[i][1] + bv1;
            o.z = acc[i][2] + bv2;
            o.w = acc[i][3] + bv3;
            *(float4*)&out[(size_t)row * M2 + c0 + tx * 4] = o;
        }
    }
}

// ---------------- GATv2 edge-softmax aggregation (dst-centric, online softmax) ----
// One block per destination node, one warp per head.
// f layout: [N][2*NH*D], fs at offset 0, fd at offset NH*D.
// hout[v][d] = max over heads of (sum_e alpha_e * fs[src_e][h][d])
template <int D>
__launch_bounds__(128)
__global__ void gat_agg(const float* __restrict__ attn) {
    constexpr int VEC = D / 32;
    constexpr int HD = NH * D;
    constexpr int F = 2 * HD;
    const float* __restrict__ f = (D == 64) ? g_f1 : g_f2;
    float* __restrict__ hout = (D == 64) ? g_h1 : g_h2;

    int v = blockIdx.x;
    int h = threadIdx.x >> 5;
    int lane = threadIdx.x & 31;

    __shared__ float sh[HD];

    int e0 = g_off[v], e1 = g_off[v + 1];

    float fdv[VEC], ar[VEC];
    {
        const float* p = f + (size_t)v * F + HD + h * D + lane * VEC;
        const float* ap = attn + h * D + lane * VEC;
        if (VEC == 2) {
            float2 t = *(const float2*)p; fdv[0] = t.x; fdv[1] = t.y;
            float2 u = *(const float2*)ap; ar[0] = u.x; ar[1] = u.y;
        } else {
            float4 t = *(const float4*)p;
            fdv[0] = t.x; fdv[1] = t.y; fdv[2] = t.z; fdv[3] = t.w;
            float4 u = *(const float4*)ap;
            ar[0] = u.x; ar[1] = u.y; ar[2] = u.z; ar[3] = u.w;
        }
    }

    float m = __int_as_float(0xff800000u);  // -inf
    float s = 0.f;
    float acc[VEC];
#pragma unroll
    for (int j = 0; j < VEC; j++) acc[j] = 0.f;

    for (int e = e0; e < e1; e++) {
        int u = g_csr[e];
        const float* p = f + (size_t)u * F + h * D + lane * VEC;
        float fsv[VEC];
        if (VEC == 2) {
            float2 t = *(const float2*)p; fsv[0] = t.x; fsv[1] = t.y;
        } else {
            float4 t = *(const float4*)p;
            fsv[0] = t.x; fsv[1] = t.y; fsv[2] = t.z; fsv[3] = t.w;
        }
        float pdot = 0.f;
#pragma unroll
        for (int j = 0; j < VEC; j++) {
            float t = fsv[j] + fdv[j];
            t = (t > 0.f) ? t : 0.2f * t;  // leaky_relu(0.2)
            pdot = fmaf(ar[j], t, pdot);
        }
#pragma unroll
        for (int o = 16; o; o >>= 1) pdot += __shfl_xor_sync(0xffffffffu, pdot, o);
        // online softmax update
        if (pdot > m) {
            float c = __expf(m - pdot);
            s *= c;
#pragma unroll
            for (int j = 0; j < VEC; j++) acc[j] *= c;
            m = pdot;
        }
        float w = __expf(pdot - m);
        s += w;
#pragma unroll
        for (int j = 0; j < VEC; j++) acc[j] = fmaf(w, fsv[j], acc[j]);
    }

    float inv = (e1 > e0) ? 1.f / s : 0.f;  // isolated node -> 0 (matches reference)
#pragma unroll
    for (int j = 0; j < VEC; j++) sh[h * D + lane * VEC + j] = acc[j] * inv;
    __syncthreads();

    for (int d = threadIdx.x; d < D; d += 128) {
        float mx = fmaxf(fmaxf(sh[d], sh[D + d]), fmaxf(sh[2 * D + d], sh[3 * D + d]));
        hout[(size_t)v * D + d] = mx;
    }
}

// ---------------- global attention pooling ----------------
// gate = h2 @ gate_w + gate_b; per-graph softmax; out[g] = sum alpha * h2
__launch_bounds__(256)
__global__ void gate_pool(const float* __restrict__ gw, const float* __restrict__ gb,
                          float* __restrict__ out) {
    int g = blockIdx.x;
    int n0 = g * NPG;
    __shared__ float sgw[128];
    __shared__ float sg[NPG];
    __shared__ float red[8];
    __shared__ float s_val;

    int tid = threadIdx.x, warp = tid >> 5, lane = tid & 31;
    if (tid < 128) sgw[tid] = gw[tid];
    __syncthreads();

    float gbv = gb[0];
    // gate logits: one warp per node
    for (int n = warp; n < NPG; n += 8) {
        const float4 hv = *(const float4*)(g_h2 + (size_t)(n0 + n) * 128 + lane * 4);
        const float4 wv = *(const float4*)(sgw + lane * 4);
        float p = hv.x * wv.x + hv.y * wv.y + hv.z * wv.z + hv.w * wv.w;
#pragma unroll
        for (int o = 16; o; o >>= 1) p += __shfl_xor_sync(0xffffffffu, p, o);
        if (lane == 0) sg[n] = p + gbv;
    }
    __syncthreads();

    // max
    float mx = __int_as_float(0xff800000u);
    for (int n = tid; n < NPG; n += 256) mx = fmaxf(mx, sg[n]);
#pragma unroll
    for (int o = 16; o; o >>= 1) mx = fmaxf(mx, __shfl_xor_sync(0xffffffffu, mx, o));
    if (lane == 0) red[warp] = mx;
    __syncthreads();
    if (tid == 0) {
        float t = red[0];
        for (int i = 1; i < 8; i++) t = fmaxf(t, red[i]);
        s_val = t;
    }
    __syncthreads();
    float gmax = s_val;
    __syncthreads();

    // exp + sum
    float ps = 0.f;
    for (int n = tid; n < NPG; n += 256) {
        float e = __expf(sg[n] - gmax);
        sg[n] = e;
        ps += e;
    }
#pragma unroll
    for (int o = 16; o; o >>= 1) ps += __shfl_xor_sync(0xffffffffu, ps, o);
    if (lane == 0) red[warp] = ps;
    __syncthreads();
    if (tid == 0) {
        float t = 0.f;
        for (int i = 0; i < 8; i++) t += red[i];
        s_val = 1.f / t;
    }
    __syncthreads();
    float sinv = s_val;

    // weighted sum per output dim
    if (tid < 128) {
        float a0 = 0.f, a1 = 0.f, a2 = 0.f, a3 = 0.f;
        for (int n = 0; n < NPG; n += 4) {
            a0 = fmaf(sg[n + 0], g_h2[(size_t)(n0 + n + 0) * 128 + tid], a0);
            a1 = fmaf(sg[n + 1], g_h2[(size_t)(n0 + n + 1) * 128 + tid], a1);
            a2 = fmaf(sg[n + 2], g_h2[(size_t)(n0 + n + 2) * 128 + tid], a2);
            a3 = fmaf(sg[n + 3], g_h2[(size_t)(n0 + n + 3) * 128 + tid], a3);
        }
        out[g * 128 + tid] = (a0 + a1 + a2 + a3) * sinv;
    }
}

// ---------------- launch ----------------
extern "C" void kernel_launch(void* const* d_in, const int* in_sizes, int n_in,
                              void* d_out, int out_size) {
    (void)in_sizes; (void)n_in; (void)out_size;
    const float* x     = (const float*)d_in[0];
    const int*   esrc  = (const int*)d_in[1];
    const int*   edst  = (const int*)d_in[2];
    /* d_in[3] node_graph: nodes are contiguous per graph (arange // 1000) */
    const float* Wl1   = (const float*)d_in[4];
    const float* bl1   = (const float*)d_in[5];
    const float* Wr1   = (const float*)d_in[6];
    const float* br1   = (const float*)d_in[7];
    const float* attn1 = (const float*)d_in[8];
    const float* Wl2   = (const float*)d_in[9];
    const float* bl2   = (const float*)d_in[10];
    const float* Wr2   = (const float*)d_in[11];
    const float* br2   = (const float*)d_in[12];
    const float* attn2 = (const float*)d_in[13];
    const float* gw    = (const float*)d_in[14];
    const float* gb    = (const float*)d_in[15];
    float* out = (float*)d_out;

    // CSR by destination (rebuilt every launch; deterministic inputs)
    k_zero_deg<<<(NNODES + 255) / 256, 256>>>();
    k_count<<<512, 256>>>(edst);
    k_scan<<<1, 1024>>>();
    k_scatter<<<512, 256>>>(esrc, edst);

    // Layer 1: fused fs/fd projection, then GATv2 aggregation + head max
    {
        dim3 grid((NNODES + 63) / 64, 512 / 64);
        gemm_bias<128, 1><<<grid, 256>>>(x, Wl1, bl1, Wr1, br1, 256);
    }
    gat_agg<64><<<NNODES, 128>>>(attn1);

    // Layer 2
    {
        dim3 grid((NNODES + 63) / 64, 1024 / 64);
        gemm_bias<64, 2><<<grid, 256>>>(nullptr, Wl2, bl2, Wr2, br2, 512);
    }
    gat_agg<128><<<NNODES, 128>>>(attn2);

    // Global attention pooling
    gate_pool<<<NGRAPH, 256>>>(gw, gb, out);
}

// round 5
// speedup vs baseline: 1.1410x; 1.1410x over previous
#include <cuda_runtime.h>

// Problem constants (fixed by the dataset)
#define NNODES 50000
#define NEDGES 500000
#define NGRAPH 50
#define NPG    1000   // nodes per graph
#define NH     4      // heads

// ---------------- scratch (device globals: allocation-free) ----------------
__device__ __align__(16) float g_f1[(size_t)NNODES * 512];    // [N][512]: fs1 | fd1
__device__ __align__(16) float g_h1[(size_t)NNODES * 64];     // layer-1 output  [N,64]
__device__ __align__(16) float g_f2[(size_t)NNODES * 1024];   // [N][1024]: fs2 | fd2
__device__ __align__(16) float g_h2[(size_t)NNODES * 128];    // layer-2 output  [N,128]
__device__ int   g_deg[NNODES];
__device__ int   g_off[NNODES + 1];
__device__ int   g_cur[NNODES];
__device__ int   g_csr[NEDGES];                 // src node per CSR slot (grouped by dst)
__device__ int   g_bsum[64];                    // block sums for hierarchical scan

// ---------------- CSR construction ----------------
__global__ void k_zero_deg() {
    int i = blockIdx.x * blockDim.x + threadIdx.x;
    if (i < NNODES) g_deg[i] = 0;
}

__global__ void k_count(const int* __restrict__ dst) {
    for (int e = blockIdx.x * blockDim.x + threadIdx.x; e < NEDGES;
         e += gridDim.x * blockDim.x)
        atomicAdd(&g_deg[dst[e]], 1);
}

// hierarchical scan: stage 1 — per-block exclusive scan of 1024 elems
__global__ void k_scan1() {
    __shared__ int sh[1024];
    int tid = threadIdx.x;
    int i = blockIdx.x * 1024 + tid;
    int v = (i < NNODES) ? g_deg[i] : 0;
    sh[tid] = v;
    __syncthreads();
#pragma unroll
    for (int o = 1; o < 1024; o <<= 1) {
        int t = (tid >= o) ? sh[tid - o] : 0;
        __syncthreads();
        sh[tid] += t;
        __syncthreads();
    }
    if (i < NNODES) g_off[i] = sh[tid] - v;   // block-local exclusive
    if (tid == 1023) g_bsum[blockIdx.x] = sh[1023];
}

// stage 2 — scan the 49 block sums (single block of 64 threads)
__global__ void k_scan2() {
    __shared__ int sh[64];
    int tid = threadIdx.x;
    int v = (tid < 49) ? g_bsum[tid] : 0;
    sh[tid] = v;
    __syncthreads();
#pragma unroll
    for (int o = 1; o < 64; o <<= 1) {
        int t = (tid >= o) ? sh[tid - o] : 0;
        __syncthreads();
        sh[tid] += t;
        __syncthreads();
    }
    if (tid < 49) g_bsum[tid] = sh[tid] - v;  // exclusive carry per block
    if (tid == 0) g_off[NNODES] = NEDGES;
}

// stage 3 — add carries, produce g_cur
__global__ void k_scan3() {
    int i = blockIdx.x * blockDim.x + threadIdx.x;
    if (i < NNODES) {
        int o = g_off[i] + g_bsum[i >> 10];
        g_off[i] = o;
        g_cur[i] = o;
    }
}

__global__ void k_scatter(const int* __restrict__ src, const int* __restrict__ dst) {
    for (int e = blockIdx.x * blockDim.x + threadIdx.x; e < NEDGES;
         e += gridDim.x * blockDim.x) {
        int pos = atomicAdd(&g_cur[dst[e]], 1);
        g_csr[pos] = src[e];
    }
}

// ---------------- fused dual GEMM + bias (128x128 tile, 8x8 microtile) ------
// out[n, c] = A[n,:] @ (c < Mh ? Wl[:,c] : Wr[:,c-Mh]) + bias
// BM=128, BN=128, BK=16, 256 threads, double-buffered SMEM.
// A-tile row stride = BM+4 = 132 floats (528B): multiple of 4 floats, so
// float4 LDS at [kk][ty*8] stays 16B-aligned (the +1 pad in R4 trapped).
// LAYER==1: A = Aparam (x), out = g_f1 ; LAYER==2: A = g_h1, out = g_f2
template <int K, int Mh, int LAYER>
__launch_bounds__(256)
__global__ void gemm_bias(const float* __restrict__ Aparam,
                          const float* __restrict__ Wl, const float* __restrict__ bl,
                          const float* __restrict__ Wr, const float* __restrict__ br) {
    constexpr int BM = 128, BN = 128, BK = 16;
    constexpr int NT = K / BK;   // k-iterations
    constexpr int AS = BM + 4;   // padded A row stride (16B-aligned)

    const float* __restrict__ A = (LAYER == 1) ? Aparam : g_h1;
    float* __restrict__ out = (LAYER == 1) ? g_f1 : g_f2;

    __shared__ __align__(16) float As[2][BK][AS];   // transposed A tile
    __shared__ __align__(16) float Bs[2][BK][BN];

    const int tid = threadIdx.x;
    const int ty = tid >> 4;        // 0..15  (row group)
    const int tx = tid & 15;        // 0..15  (col group)
    const int r0 = blockIdx.x * BM;
    const int c0g = blockIdx.y * BN;            // global col in [0, 2*Mh)

    const float* W;
    const float* b;
    int cc0;
    if (c0g < Mh) { W = Wl; b = bl; cc0 = c0g; }
    else          { W = Wr; b = br; cc0 = c0g - Mh; }

    // A tile load map: 512 float4 (128 rows x 4 float4), 2 per thread
    const int aRow0 = tid >> 2;            // rows 0..63
    const int aK0   = (tid & 3) * 4;
    const int aRow1 = (tid + 256) >> 2;    // rows 64..127
    // B tile load map: 512 float4 (16 rows x 32 float4), 2 per thread
    const int bRow0 = tid >> 5;            // 0..7
    const int bC0   = (tid & 31) * 4;
    const int bRow1 = (tid + 256) >> 5;    // 8..15

    float4 aT0, aT1, bT0, bT1;

    // prologue: load tile 0
    {
        int gr0 = r0 + aRow0, gr1 = r0 + aRow1;
        aT0 = (gr0 < NNODES) ? *(const float4*)&A[(size_t)gr0 * K + aK0]
                             : make_float4(0.f, 0.f, 0.f, 0.f);
        aT1 = (gr1 < NNODES) ? *(const float4*)&A[(size_t)gr1 * K + aK0]
                             : make_float4(0.f, 0.f, 0.f, 0.f);
        bT0 = *(const float4*)&W[(size_t)bRow0 * Mh + cc0 + bC0];
        bT1 = *(const float4*)&W[(size_t)bRow1 * Mh + cc0 + bC0];
        As[0][aK0 + 0][aRow0] = aT0.x; As[0][aK0 + 1][aRow0] = aT0.y;
        As[0][aK0 + 2][aRow0] = aT0.z; As[0][aK0 + 3][aRow0] = aT0.w;
        As[0][aK0 + 0][aRow1] = aT1.x; As[0][aK0 + 1][aRow1] = aT1.y;
        As[0][aK0 + 2][aRow1] = aT1.z; As[0][aK0 + 3][aRow1] = aT1.w;
        *(float4*)&Bs[0][bRow0][bC0] = bT0;
        *(float4*)&Bs[0][bRow1][bC0] = bT1;
    }
    __syncthreads();

    float acc[8][8] = {};

#pragma unroll
    for (int t = 0; t < NT; t++) {
        const int cur = t & 1;
        // prefetch next tile into registers
        if (t + 1 < NT) {
            const int kb = (t + 1) * BK;
            int gr0 = r0 + aRow0, gr1 = r0 + aRow1;
            aT0 = (gr0 < NNODES) ? *(const float4*)&A[(size_t)gr0 * K + kb + aK0]
                                 : make_float4(0.f, 0.f, 0.f, 0.f);
            aT1 = (gr1 < NNODES) ? *(const float4*)&A[(size_t)gr1 * K + kb + aK0]
                                 : make_float4(0.f, 0.f, 0.f, 0.f);
            bT0 = *(const float4*)&W[(size_t)(kb + bRow0) * Mh + cc0 + bC0];
            bT1 = *(const float4*)&W[(size_t)(kb + bRow1) * Mh + cc0 + bC0];
        }
        // compute on buffer `cur`
#pragma unroll
        for (int kk = 0; kk < BK; kk++) {
            float4 a0 = *(const float4*)&As[cur][kk][ty * 8];
            float4 a1 = *(const float4*)&As[cur][kk][ty * 8 + 4];
            float4 b0 = *(const float4*)&Bs[cur][kk][tx * 8];
            float4 b1 = *(const float4*)&Bs[cur][kk][tx * 8 + 4];
            float ar[8] = {a0.x, a0.y, a0.z, a0.w, a1.x, a1.y, a1.z, a1.w};
            float br_[8] = {b0.x, b0.y, b0.z, b0.w, b1.x, b1.y, b1.z, b1.w};
#pragma unroll
            for (int i = 0; i < 8; i++)
#pragma unroll
                for (int j = 0; j < 8; j++)
                    acc[i][j] = fmaf(ar[i], br_[j], acc[i][j]);
        }
        // stage next tile into the other buffer
        if (t + 1 < NT) {
            const int nxt = cur ^ 1;
            As[nxt][aK0 + 0][aRow0] = aT0.x; As[nxt][aK0 + 1][aRow0] = aT0.y;
            As[nxt][aK0 + 2][aRow0] = aT0.z; As[nxt][aK0 + 3][aRow0] = aT0.w;
            As[nxt][aK0 + 0][aRow1] = aT1.x; As[nxt][aK0 + 1][aRow1] = aT1.y;
            As[nxt][aK0 + 2][aRow1] = aT1.z; As[nxt][aK0 + 3][aRow1] = aT1.w;
            *(float4*)&Bs[nxt][bRow0][bC0] = bT0;
            *(float4*)&Bs[nxt][bRow1][bC0] = bT1;
            __syncthreads();
        }
    }

    // epilogue: bias + store
    float bias[8];
#pragma unroll
    for (int j = 0; j < 8; j++) bias[j] = b[cc0 + tx * 8 + j];
    constexpr int M2 = 2 * Mh;
#pragma unroll
    for (int i = 0; i < 8; i++) {
        int row = r0 + ty * 8 + i;
        if (row < NNODES) {
            float4 o0, o1;
            o0.x = acc[i][0] + bias[0]; o0.y = acc[i][1] + bias[1];
            o0.z = acc[i][2] + bias[2]; o0.w = acc[i][3] + bias[3];
            o1.x = acc[i][4] + bias[4]; o1.y = acc[i][5] + bias[5];
            o1.z = acc[i][6] + bias[6]; o1.w = acc[i][7] + bias[7];
            *(float4*)&out[(size_t)row * M2 + c0g + tx * 8]     = o0;
            *(float4*)&out[(size_t)row * M2 + c0g + tx * 8 + 4] = o1;
        }
    }
}

// ---------------- GATv2 edge-softmax aggregation (dst-centric, online softmax) ----
// One block per destination node, one warp per head.
// f layout: [N][2*NH*D], fs at offset 0, fd at offset NH*D.
// hout[v][d] = max over heads of (sum_e alpha_e * fs[src_e][h][d])
template <int D>
__launch_bounds__(128)
__global__ void gat_agg(const float* __restrict__ attn) {
    constexpr int VEC = D / 32;
    constexpr int HD = NH * D;
    constexpr int F = 2 * HD;
    const float* __restrict__ f = (D == 64) ? g_f1 : g_f2;
    float* __restrict__ hout = (D == 64) ? g_h1 : g_h2;

    int v = blockIdx.x;
    int h = threadIdx.x >> 5;
    int lane = threadIdx.x & 31;

    __shared__ float sh[HD];

    int e0 = g_off[v], e1 = g_off[v + 1];

    float fdv[VEC], ar[VEC];
    {
        const float* p = f + (size_t)v * F + HD + h * D + lane * VEC;
        const float* ap = attn + h * D + lane * VEC;
        if (VEC == 2) {
            float2 t = *(const float2*)p; fdv[0] = t.x; fdv[1] = t.y;
            float2 u = *(const float2*)ap; ar[0] = u.x; ar[1] = u.y;
        } else {
            float4 t = *(const float4*)p;
            fdv[0] = t.x; fdv[1] = t.y; fdv[2] = t.z; fdv[3] = t.w;
            float4 u = *(const float4*)ap;
            ar[0] = u.x; ar[1] = u.y; ar[2] = u.z; ar[3] = u.w;
        }
    }

    float m = __int_as_float(0xff800000u);  // -inf
    float s = 0.f;
    float acc[VEC];
#pragma unroll
    for (int j = 0; j < VEC; j++) acc[j] = 0.f;

    for (int e = e0; e < e1; e++) {
        int u = g_csr[e];
        const float* p = f + (size_t)u * F + h * D + lane * VEC;
        float fsv[VEC];
        if (VEC == 2) {
            float2 t = *(const float2*)p; fsv[0] = t.x; fsv[1] = t.y;
        } else {
            float4 t = *(const float4*)p;
            fsv[0] = t.x; fsv[1] = t.y; fsv[2] = t.z; fsv[3] = t.w;
        }
        float pdot = 0.f;
#pragma unroll
        for (int j = 0; j < VEC; j++) {
            float t = fsv[j] + fdv[j];
            t = (t > 0.f) ? t : 0.2f * t;  // leaky_relu(0.2)
            pdot = fmaf(ar[j], t, pdot);
        }
#pragma unroll
        for (int o = 16; o; o >>= 1) pdot += __shfl_xor_sync(0xffffffffu, pdot, o);
        // online softmax update
        if (pdot > m) {
            float c = __expf(m - pdot);
            s *= c;
#pragma unroll
            for (int j = 0; j < VEC; j++) acc[j] *= c;
            m = pdot;
        }
        float w = __expf(pdot - m);
        s += w;
#pragma unroll
        for (int j = 0; j < VEC; j++) acc[j] = fmaf(w, fsv[j], acc[j]);
    }

    float inv = (e1 > e0) ? 1.f / s : 0.f;  // isolated node -> 0 (matches reference)
#pragma unroll
    for (int j = 0; j < VEC; j++) sh[h * D + lane * VEC + j] = acc[j] * inv;
    __syncthreads();

    for (int d = threadIdx.x; d < D; d += 128) {
        float mx = fmaxf(fmaxf(sh[d], sh[D + d]), fmaxf(sh[2 * D + d], sh[3 * D + d]));
        hout[(size_t)v * D + d] = mx;
    }
}

// ---------------- global attention pooling (512 threads / graph) -----------
__launch_bounds__(512)
__global__ void gate_pool(const float* __restrict__ gw, const float* __restrict__ gb,
                          float* __restrict__ out) {
    int g = blockIdx.x;
    int n0 = g * NPG;
    __shared__ __align__(16) float sgw[128];
    __shared__ float sg[NPG];
    __shared__ float red[16];
    __shared__ float partial[4][128];
    __shared__ float s_val;

    int tid = threadIdx.x, warp = tid >> 5, lane = tid & 31;
    if (tid < 128) sgw[tid] = gw[tid];
    __syncthreads();

    float gbv = gb[0];
    // gate logits: one warp per node, 16 warps
    for (int n = warp; n < NPG; n += 16) {
        const float4 hv = *(const float4*)(g_h2 + (size_t)(n0 + n) * 128 + lane * 4);
        const float4 wv = *(const float4*)(sgw + lane * 4);
        float p = hv.x * wv.x + hv.y * wv.y + hv.z * wv.z + hv.w * wv.w;
#pragma unroll
        for (int o = 16; o; o >>= 1) p += __shfl_xor_sync(0xffffffffu, p, o);
        if (lane == 0) sg[n] = p + gbv;
    }
    __syncthreads();

    // max
    float mx = __int_as_float(0xff800000u);
    for (int n = tid; n < NPG; n += 512) mx = fmaxf(mx, sg[n]);
#pragma unroll
    for (int o = 16; o; o >>= 1) mx = fmaxf(mx, __shfl_xor_sync(0xffffffffu, mx, o));
    if (lane == 0) red[warp] = mx;
    __syncthreads();
    if (tid == 0) {
        float t = red[0];
        for (int i = 1; i < 16; i++) t = fmaxf(t, red[i]);
        s_val = t;
    }
    __syncthreads();
    float gmax = s_val;
    __syncthreads();

    // exp + sum
    float ps = 0.f;
    for (int n = tid; n < NPG; n += 512) {
        float e = __expf(sg[n] - gmax);
        sg[n] = e;
        ps += e;
    }
#pragma unroll
    for (int o = 16; o; o >>= 1) ps += __shfl_xor_sync(0xffffffffu, ps, o);
    if (lane == 0) red[warp] = ps;
    __syncthreads();
    if (tid == 0) {
        float t = 0.f;
        for (int i = 0; i < 16; i++) t += red[i];
        s_val = 1.f / t;
    }
    __syncthreads();
    float sinv = s_val;

    // weighted sum: 4 row-groups x 128 dims
    int grp = tid >> 7;         // 0..3
    int d = tid & 127;
    float a0 = 0.f, a1 = 0.f;
    int nA = grp * 250, nB = nA + 250;
    for (int n = nA; n < nB; n += 2) {
        a0 = fmaf(sg[n + 0], g_h2[(size_t)(n0 + n + 0) * 128 + d], a0);
        a1 = fmaf(sg[n + 1], g_h2[(size_t)(n0 + n + 1) * 128 + d], a1);
    }
    partial[grp][d] = a0 + a1;
    __syncthreads();
    if (tid < 128) {
        out[g * 128 + tid] =
            (partial[0][tid] + partial[1][tid] + partial[2][tid] + partial[3][tid]) * sinv;
    }
}

// ---------------- launch ----------------
extern "C" void kernel_launch(void* const* d_in, const int* in_sizes, int n_in,
                              void* d_out, int out_size) {
    (void)in_sizes; (void)n_in; (void)out_size;
    const float* x     = (const float*)d_in[0];
    const int*   esrc  = (const int*)d_in[1];
    const int*   edst  = (const int*)d_in[2];
    /* d_in[3] node_graph: nodes are contiguous per graph (arange // 1000) */
    const float* Wl1   = (const float*)d_in[4];
    const float* bl1   = (const float*)d_in[5];
    const float* Wr1   = (const float*)d_in[6];
    const float* br1   = (const float*)d_in[7];
    const float* attn1 = (const float*)d_in[8];
    const float* Wl2   = (const float*)d_in[9];
    const float* bl2   = (const float*)d_in[10];
    const float* Wr2   = (const float*)d_in[11];
    const float* br2   = (const float*)d_in[12];
    const float* attn2 = (const float*)d_in[13];
    const float* gw    = (const float*)d_in[14];
    const float* gb    = (const float*)d_in[15];
    float* out = (float*)d_out;

    // CSR by destination
    k_zero_deg<<<(NNODES + 255) / 256, 256>>>();
    k_count<<<512, 256>>>(edst);
    k_scan1<<<49, 1024>>>();
    k_scan2<<<1, 64>>>();
    k_scan3<<<(NNODES + 255) / 256, 256>>>();
    k_scatter<<<512, 256>>>(esrc, edst);

    const int RB = (NNODES + 127) / 128;   // 391 row blocks

    // Layer 1: fused fs/fd projection, then GATv2 aggregation + head max
    gemm_bias<128, 256, 1><<<dim3(RB, 4), 256>>>(x, Wl1, bl1, Wr1, br1);
    gat_agg<64><<<NNODES, 128>>>(attn1);

    // Layer 2
    gemm_bias<64, 512, 2><<<dim3(RB, 8), 256>>>(nullptr, Wl2, bl2, Wr2, br2);
    gat_agg<128><<<NNODES, 128>>>(attn2);

    // Global attention pooling
    gate_pool<<<NGRAPH, 512>>>(gw, gb, out);
}

// round 8
// speedup vs baseline: 1.5422x; 1.3516x over previous
#include <cuda_runtime.h>
#include <cuda_bf16.h>
#include <cstdint>

// Problem constants (fixed by the dataset)
#define NNODES 50000
#define NEDGES 500000
#define NGRAPH 50
#define NPG    1000   // nodes per graph
#define NH     4      // heads

// ---------------- scratch (device globals: allocation-free) ----------------
__device__ __align__(16) float g_f1[(size_t)NNODES * 512];    // [N][512]: fs1 | fd1
__device__ __align__(16) float g_f2[(size_t)NNODES * 1024];   // [N][1024]: fs2 | fd2
__device__ __align__(16) float g_h2[(size_t)NNODES * 128];    // layer-2 output [N,128]
// bf16 two-term splits of the GEMM A operand (x for layer1, h1 for layer2)
__device__ __align__(16) __nv_bfloat16 g_ahi[(size_t)NNODES * 128];
__device__ __align__(16) __nv_bfloat16 g_alo[(size_t)NNODES * 128];
// W^T splits: [2*Mh][K], max 65536 elements
__device__ __align__(16) __nv_bfloat16 g_wthi[65536];
__device__ __align__(16) __nv_bfloat16 g_wtlo[65536];
__device__ int g_deg[NNODES];
__device__ int g_off[NNODES + 1];
__device__ int g_cur[NNODES];
__device__ int g_csr[NEDGES];
__device__ int g_bsum[64];

// ---------------- PTX helpers (baseline PTX only: no tcgen05) ----------------
__device__ __forceinline__ uint32_t smem_u32(const void* p) {
    uint32_t a;
    asm("{ .reg .u64 t; cvta.to.shared.u64 t, %1; cvt.u32.u64 %0, t; }"
        : "=r"(a) : "l"(p));
    return a;
}

#define CP16(dst, src, nbytes) \
    asm volatile("cp.async.ca.shared.global [%0], [%1], 16, %2;" \
                 :: "r"(dst), "l"(src), "r"(nbytes) : "memory")
#define CP_COMMIT() asm volatile("cp.async.commit_group;" ::: "memory")
#define CP_WAIT0()  asm volatile("cp.async.wait_group 0;" ::: "memory")
#define CP_WAIT1()  asm volatile("cp.async.wait_group 1;" ::: "memory")

// D(f32) += A(bf16) @ B(bf16): m16n8k16, A row-major, B col-major
__device__ __forceinline__ void mma_bf16(float* d, const uint32_t* a, const uint32_t* b) {
    asm volatile(
        "mma.sync.aligned.m16n8k16.row.col.f32.bf16.bf16.f32 "
        "{%0,%1,%2,%3}, {%4,%5,%6,%7}, {%8,%9}, {%0,%1,%2,%3};"
        : "+f"(d[0]), "+f"(d[1]), "+f"(d[2]), "+f"(d[3])
        : "r"(a[0]), "r"(a[1]), "r"(a[2]), "r"(a[3]), "r"(b[0]), "r"(b[1]));
}

// ---------------- CSR construction ----------------
__global__ void k_zero_deg() {
    int i = blockIdx.x * blockDim.x + threadIdx.x;
    if (i < NNODES) g_deg[i] = 0;
}

__global__ void k_count(const int* __restrict__ dst) {
    for (int e = blockIdx.x * blockDim.x + threadIdx.x; e < NEDGES;
         e += gridDim.x * blockDim.x)
        atomicAdd(&g_deg[dst[e]], 1);
}

__global__ void k_scan1() {
    __shared__ int sh[1024];
    int tid = threadIdx.x;
    int i = blockIdx.x * 1024 + tid;
    int v = (i < NNODES) ? g_deg[i] : 0;
    sh[tid] = v;
    __syncthreads();
#pragma unroll
    for (int o = 1; o < 1024; o <<= 1) {
        int t = (tid >= o) ? sh[tid - o] : 0;
        __syncthreads();
        sh[tid] += t;
        __syncthreads();
    }
    if (i < NNODES) g_off[i] = sh[tid] - v;
    if (tid == 1023) g_bsum[blockIdx.x] = sh[1023];
}

__global__ void k_scan2() {
    __shared__ int sh[64];
    int tid = threadIdx.x;
    int v = (tid < 49) ? g_bsum[tid] : 0;
    sh[tid] = v;
    __syncthreads();
#pragma unroll
    for (int o = 1; o < 64; o <<= 1) {
        int t = (tid >= o) ? sh[tid - o] : 0;
        __syncthreads();
        sh[tid] += t;
        __syncthreads();
    }
    if (tid < 49) g_bsum[tid] = sh[tid] - v;
    if (tid == 0) g_off[NNODES] = NEDGES;
}

__global__ void k_scan3() {
    int i = blockIdx.x * blockDim.x + threadIdx.x;
    if (i < NNODES) {
        int o = g_off[i] + g_bsum[i >> 10];
        g_off[i] = o;
        g_cur[i] = o;
    }
}

__global__ void k_scatter(const int* __restrict__ src, const int* __restrict__ dst) {
    for (int e = blockIdx.x * blockDim.x + threadIdx.x; e < NEDGES;
         e += gridDim.x * blockDim.x) {
        int pos = atomicAdd(&g_cur[dst[e]], 1);
        g_csr[pos] = src[e];
    }
}

// ---------------- bf16 hi/lo split of x ----------------
__global__ void k_split_x(const float* __restrict__ x) {
    for (int i = blockIdx.x * blockDim.x + threadIdx.x; i < NNODES * 128;
         i += gridDim.x * blockDim.x) {
        float v = x[i];
        __nv_bfloat16 h = __float2bfloat16(v);
        g_ahi[i] = h;
        g_alo[i] = __float2bfloat16(v - __bfloat162float(h));
    }
}

// ---------------- W^T + bf16 split: g_wt*[c][k] = split(W[k][c]) ----------
__global__ void k_prepw(const float* __restrict__ Wl, const float* __restrict__ Wr,
                        int Mh, int K) {
    int idx = blockIdx.x * blockDim.x + threadIdx.x;
    int tot = 2 * Mh * K;
    if (idx >= tot) return;
    int c = idx % (2 * Mh);
    int k = idx / (2 * Mh);
    float v = (c < Mh) ? Wl[(size_t)k * Mh + c] : Wr[(size_t)k * Mh + (c - Mh)];
    __nv_bfloat16 h = __float2bfloat16(v);
    g_wthi[(size_t)c * K + k] = h;
    g_wtlo[(size_t)c * K + k] = __float2bfloat16(v - __bfloat162float(h));
}

// ---------------- bf16x3 mma.sync GEMM ----------------
// out[n, 2Mh] = A @ W^T + bias via Ah·Bh + Ah·Bl + Al·Bh (f32 accumulate).
// Block tile 128 rows x 64 cols, 8 warps (4x2), warp tile 32x32.
// BK=32, cp.async double buffer. SMEM rows padded to 80B (conflict-free lds).
template <int K, int Mh, int LAYER>
__launch_bounds__(256, 2)
__global__ void gemm_bf16(const float* __restrict__ bl, const float* __restrict__ br) {
    constexpr int NT = K / 32;
    constexpr int T_AH = 0, T_AL = 10240, T_BH = 20480, T_BL = 25600, STG = 30720;
    float* __restrict__ out = (LAYER == 1) ? g_f1 : g_f2;

    extern __shared__ __align__(16) char sm[];
    const uint32_t smb = smem_u32(sm);

    const int tid = threadIdx.x, wid = tid >> 5, lane = tid & 31;
    const int g = lane >> 2, t = lane & 3;
    const int wm = wid & 3, wn = wid >> 2;           // 4 x 2 warp grid
    const int r0 = blockIdx.x * 128;
    const int c0 = blockIdx.y * 64;

    // per-thread fill coordinates
    const int aRowA = tid >> 2, aQ = tid & 3;        // A: 2 uint4/thread/tile
    const int aRowB = (tid + 256) >> 2;
    const int bRow = tid >> 2, bQ = tid & 3;         // B: 1 uint4/thread/tile

    auto fill = [&](int buf, int kb) {
        uint32_t bo = smb + buf * STG;
        // A hi/lo tiles: 128 rows x 32 bf16
        {
            int gr = r0 + aRowA;
            int grc = (gr < NNODES) ? gr : (NNODES - 1);
            int n = (gr < NNODES) ? 16 : 0;
            uint32_t d = bo + aRowA * 80 + aQ * 16;
            const char* s1 = (const char*)g_ahi + ((size_t)grc * K + kb + aQ * 8) * 2;
            const char* s2 = (const char*)g_alo + ((size_t)grc * K + kb + aQ * 8) * 2;
            CP16(d + T_AH, s1, n);
            CP16(d + T_AL, s2, n);
        }
        {
            int gr = r0 + aRowB;
            int grc = (gr < NNODES) ? gr : (NNODES - 1);
            int n = (gr < NNODES) ? 16 : 0;
            uint32_t d = bo + aRowB * 80 + aQ * 16;
            const char* s1 = (const char*)g_ahi + ((size_t)grc * K + kb + aQ * 8) * 2;
            const char* s2 = (const char*)g_alo + ((size_t)grc * K + kb + aQ * 8) * 2;
            CP16(d + T_AH, s1, n);
            CP16(d + T_AL, s2, n);
        }
        // B hi/lo tiles: 64 rows (cols of out) x 32 bf16
        {
            uint32_t d = bo + bRow * 80 + bQ * 16;
            const char* s1 = (const char*)g_wthi + ((size_t)(c0 + bRow) * K + kb + bQ * 8) * 2;
            const char* s2 = (const char*)g_wtlo + ((size_t)(c0 + bRow) * K + kb + bQ * 8) * 2;
            CP16(d + T_BH, s1, 16);
            CP16(d + T_BL, s2, 16);
        }
    };

    float acc[2][4][4] = {};

    fill(0, 0);
    CP_COMMIT();

    for (int s = 0; s < NT; s++) {
        if (s + 1 < NT) {
            fill((s + 1) & 1, (s + 1) * 32);
            CP_COMMIT();
            CP_WAIT1();
        } else {
            CP_WAIT0();
        }
        __syncthreads();
        const char* bo = sm + (s & 1) * STG;
#pragma unroll
        for (int ks = 0; ks < 2; ks++) {
            const int ksb = ks * 32;   // 16 bf16 = 32 bytes
            uint32_t ah[2][4], al[2][4];
#pragma unroll
            for (int mi = 0; mi < 2; mi++) {
                const char* p = bo + (wm * 32 + mi * 16 + g) * 80 + ksb + t * 4;
                ah[mi][0] = *(const uint32_t*)(p + T_AH);
                ah[mi][1] = *(const uint32_t*)(p + T_AH + 640);
                ah[mi][2] = *(const uint32_t*)(p + T_AH + 16);
                ah[mi][3] = *(const uint32_t*)(p + T_AH + 656);
                al[mi][0] = *(const uint32_t*)(p + T_AL);
                al[mi][1] = *(const uint32_t*)(p + T_AL + 640);
                al[mi][2] = *(const uint32_t*)(p + T_AL + 16);
                al[mi][3] = *(const uint32_t*)(p + T_AL + 656);
            }
            uint32_t bh[4][2], blr[4][2];
#pragma unroll
            for (int ni = 0; ni < 4; ni++) {
                const char* p = bo + (wn * 32 + ni * 8 + g) * 80 + ksb + t * 4;
                bh[ni][0] = *(const uint32_t*)(p + T_BH);
                bh[ni][1] = *(const uint32_t*)(p + T_BH + 16);
                blr[ni][0] = *(const uint32_t*)(p + T_BL);
                blr[ni][1] = *(const uint32_t*)(p + T_BL + 16);
            }
#pragma unroll
            for (int mi = 0; mi < 2; mi++)
#pragma unroll
                for (int ni = 0; ni < 4; ni++) {
                    mma_bf16(acc[mi][ni], ah[mi], bh[ni]);
                    mma_bf16(acc[mi][ni], ah[mi], blr[ni]);
                    mma_bf16(acc[mi][ni], al[mi], bh[ni]);
                }
        }
        __syncthreads();
    }

    // epilogue: bias + store (c0,c1 -> row g; c2,c3 -> row g+8)
    const float* bb = (c0 < Mh) ? (bl + c0) : (br + (c0 - Mh));
    constexpr int M2 = 2 * Mh;
#pragma unroll
    for (int mi = 0; mi < 2; mi++) {
#pragma unroll
        for (int ni = 0; ni < 4; ni++) {
            int lc = wn * 32 + ni * 8 + 2 * t;
            float2 bv = *(const float2*)&bb[lc];
            int row0 = r0 + wm * 32 + mi * 16 + g;
            int col = c0 + lc;
            if (row0 < NNODES) {
                float2 o;
                o.x = acc[mi][ni][0] + bv.x;
                o.y = acc[mi][ni][1] + bv.y;
                *(float2*)&out[(size_t)row0 * M2 + col] = o;
            }
            int row1 = row0 + 8;
            if (row1 < NNODES) {
                float2 o;
                o.x = acc[mi][ni][2] + bv.x;
                o.y = acc[mi][ni][3] + bv.y;
                *(float2*)&out[(size_t)row1 * M2 + col] = o;
            }
        }
    }
}

// ---------------- GATv2 edge-softmax aggregation (dst-centric, online softmax) ----
// D==64 writes its result as bf16 hi/lo splits (layer-2 GEMM input);
// D==128 writes f32 g_h2.
template <int D>
__launch_bounds__(128)
__global__ void gat_agg(const float* __restrict__ attn) {
    constexpr int VEC = D / 32;
    constexpr int HD = NH * D;
    constexpr int F = 2 * HD;
    const float* __restrict__ f = (D == 64) ? g_f1 : g_f2;

    int v = blockIdx.x;
    int h = threadIdx.x >> 5;
    int lane = threadIdx.x & 31;

    __shared__ float sh[HD];

    int e0 = g_off[v], e1 = g_off[v + 1];

    float fdv[VEC], ar[VEC];
    {
        const float* p = f + (size_t)v * F + HD + h * D + lane * VEC;
        const float* ap = attn + h * D + lane * VEC;
        if (VEC == 2) {
            float2 t = *(const float2*)p; fdv[0] = t.x; fdv[1] = t.y;
            float2 u = *(const float2*)ap; ar[0] = u.x; ar[1] = u.y;
        } else {
            float4 t = *(const float4*)p;
            fdv[0] = t.x; fdv[1] = t.y; fdv[2] = t.z; fdv[3] = t.w;
            float4 u = *(const float4*)ap;
            ar[0] = u.x; ar[1] = u.y; ar[2] = u.z; ar[3] = u.w;
        }
    }

    float m = __int_as_float(0xff800000u);  // -inf
    float s = 0.f;
    float acc[VEC];
#pragma unroll
    for (int j = 0; j < VEC; j++) acc[j] = 0.f;

    for (int e = e0; e < e1; e++) {
        int u = g_csr[e];
        const float* p = f + (size_t)u * F + h * D + lane * VEC;
        float fsv[VEC];
        if (VEC == 2) {
            float2 t = *(const float2*)p; fsv[0] = t.x; fsv[1] = t.y;
        } else {
            float4 t = *(const float4*)p;
            fsv[0] = t.x; fsv[1] = t.y; fsv[2] = t.z; fsv[3] = t.w;
        }
        float pdot = 0.f;
#pragma unroll
        for (int j = 0; j < VEC; j++) {
            float t = fsv[j] + fdv[j];
            t = (t > 0.f) ? t : 0.2f * t;  // leaky_relu(0.2)
            pdot = fmaf(ar[j], t, pdot);
        }
#pragma unroll
        for (int o = 16; o; o >>= 1) pdot += __shfl_xor_sync(0xffffffffu, pdot, o);
        if (pdot > m) {
            float c = __expf(m - pdot);
            s *= c;
#pragma unroll
            for (int j = 0; j < VEC; j++) acc[j] *= c;
            m = pdot;
        }
        float w = __expf(pdot - m);
        s += w;
#pragma unroll
        for (int j = 0; j < VEC; j++) acc[j] = fmaf(w, fsv[j], acc[j]);
    }

    float inv = (e1 > e0) ? 1.f / s : 0.f;  // isolated node -> 0
#pragma unroll
    for (int j = 0; j < VEC; j++) sh[h * D + lane * VEC + j] = acc[j] * inv;
    __syncthreads();

    for (int d = threadIdx.x; d < D; d += 128) {
        float mx = fmaxf(fmaxf(sh[d], sh[D + d]), fmaxf(sh[2 * D + d], sh[3 * D + d]));
        if (D == 64) {
            __nv_bfloat16 hh = __float2bfloat16(mx);
            g_ahi[(size_t)v * 64 + d] = hh;
            g_alo[(size_t)v * 64 + d] = __float2bfloat16(mx - __bfloat162float(hh));
        } else {
            g_h2[(size_t)v * D + d] = mx;
        }
    }
}

// ---------------- global attention pooling (512 threads / graph) -----------
__launch_bounds__(512)
__global__ void gate_pool(const float* __restrict__ gw, const float* __restrict__ gb,
                          float* __restrict__ out) {
    int g = blockIdx.x;
    int n0 = g * NPG;
    __shared__ __align__(16) float sgw[128];
    __shared__ float sg[NPG];
    __shared__ float red[16];
    __shared__ float partial[4][128];
    __shared__ float s_val;

    int tid = threadIdx.x, warp = tid >> 5, lane = tid & 31;
    if (tid < 128) sgw[tid] = gw[tid];
    __syncthreads();

    float gbv = gb[0];
    for (int n = warp; n < NPG; n += 16) {
        const float4 hv = *(const float4*)(g_h2 + (size_t)(n0 + n) * 128 + lane * 4);
        const float4 wv = *(const float4*)(sgw + lane * 4);
        float p = hv.x * wv.x + hv.y * wv.y + hv.z * wv.z + hv.w * wv.w;
#pragma unroll
        for (int o = 16; o; o >>= 1) p += __shfl_xor_sync(0xffffffffu, p, o);
        if (lane == 0) sg[n] = p + gbv;
    }
    __syncthreads();

    float mx = __int_as_float(0xff800000u);
    for (int n = tid; n < NPG; n += 512) mx = fmaxf(mx, sg[n]);
#pragma unroll
    for (int o = 16; o; o >>= 1) mx = fmaxf(mx, __shfl_xor_sync(0xffffffffu, mx, o));
    if (lane == 0) red[warp] = mx;
    __syncthreads();
    if (tid == 0) {
        float t = red[0];
        for (int i = 1; i < 16; i++) t = fmaxf(t, red[i]);
        s_val = t;
    }
    __syncthreads();
    float gmax = s_val;
    __syncthreads();

    float ps = 0.f;
    for (int n = tid; n < NPG; n += 512) {
        float e = __expf(sg[n] - gmax);
        sg[n] = e;
        ps += e;
    }
#pragma unroll
    for (int o = 16; o; o >>= 1) ps += __shfl_xor_sync(0xffffffffu, ps, o);
    if (lane == 0) red[warp] = ps;
    __syncthreads();
    if (tid == 0) {
        float t = 0.f;
        for (int i = 0; i < 16; i++) t += red[i];
        s_val = 1.f / t;
    }
    __syncthreads();
    float sinv = s_val;

    int grp = tid >> 7;
    int d = tid & 127;
    float a0 = 0.f, a1 = 0.f;
    int nA = grp * 250, nB = nA + 250;
    for (int n = nA; n < nB; n += 2) {
        a0 = fmaf(sg[n + 0], g_h2[(size_t)(n0 + n + 0) * 128 + d], a0);
        a1 = fmaf(sg[n + 1], g_h2[(size_t)(n0 + n + 1) * 128 + d], a1);
    }
    partial[grp][d] = a0 + a1;
    __syncthreads();
    if (tid < 128) {
        out[g * 128 + tid] =
            (partial[0][tid] + partial[1][tid] + partial[2][tid] + partial[3][tid]) * sinv;
    }
}

// ---------------- launch ----------------
extern "C" void kernel_launch(void* const* d_in, const int* in_sizes, int n_in,
                              void* d_out, int out_size) {
    (void)in_sizes; (void)n_in; (void)out_size;
    const float* x     = (const float*)d_in[0];
    const int*   esrc  = (const int*)d_in[1];
    const int*   edst  = (const int*)d_in[2];
    const float* Wl1   = (const float*)d_in[4];
    const float* bl1   = (const float*)d_in[5];
    const float* Wr1   = (const float*)d_in[6];
    const float* br1   = (const float*)d_in[7];
    const float* attn1 = (const float*)d_in[8];
    const float* Wl2   = (const float*)d_in[9];
    const float* bl2   = (const float*)d_in[10];
    const float* Wr2   = (const float*)d_in[11];
    const float* br2   = (const float*)d_in[12];
    const float* attn2 = (const float*)d_in[13];
    const float* gw    = (const float*)d_in[14];
    const float* gb    = (const float*)d_in[15];
    float* out = (float*)d_out;

    const int SMEM_GEMM = 61440;   // 2 stages x 30720
    // unguarded (no static state) — proven harness-safe in R5
    cudaFuncSetAttribute(gemm_bf16<128, 256, 1>,
                         cudaFuncAttributeMaxDynamicSharedMemorySize, SMEM_GEMM);
    cudaFuncSetAttribute(gemm_bf16<64, 512, 2>,
                         cudaFuncAttributeMaxDynamicSharedMemorySize, SMEM_GEMM);

    // CSR by destination + x split
    k_split_x<<<512, 256>>>(x);
    k_zero_deg<<<(NNODES + 255) / 256, 256>>>();
    k_count<<<512, 256>>>(edst);
    k_scan1<<<49, 1024>>>();
    k_scan2<<<1, 64>>>();
    k_scan3<<<(NNODES + 255) / 256, 256>>>();
    k_scatter<<<512, 256>>>(esrc, edst);

    const int RB = (NNODES + 127) / 128;   // 391 row blocks

    // Layer 1
    k_prepw<<<(2 * 256 * 128 + 255) / 256, 256>>>(Wl1, Wr1, 256, 128);
    gemm_bf16<128, 256, 1><<<dim3(RB, 8), 256, SMEM_GEMM>>>(bl1, br1);
    gat_agg<64><<<NNODES, 128>>>(attn1);   // writes bf16 splits for layer 2

    // Layer 2
    k_prepw<<<(2 * 512 * 64 + 255) / 256, 256>>>(Wl2, Wr2, 512, 64);
    gemm_bf16<64, 512, 2><<<dim3(RB, 16), 256, SMEM_GEMM>>>(bl2, br2);
    gat_agg<128><<<NNODES, 128>>>(attn2);

    // Global attention pooling
    gate_pool<<<NGRAPH, 512>>>(gw, gb, out);
}

// round 9
// speedup vs baseline: 1.5676x; 1.0165x over previous
#include <cuda_runtime.h>
#include <cuda_bf16.h>
#include <cstdint>

// Problem constants (fixed by the dataset)
#define NNODES 50000
#define NEDGES 500000
#define NGRAPH 50
#define NPG    1000   // nodes per graph
#define NH     4      // heads

// ---------------- scratch (device globals: allocation-free) ----------------
__device__ __align__(16) float g_f1[(size_t)NNODES * 512];    // [N][512]: fs1 | fd1
__device__ __align__(16) float g_f2[(size_t)NNODES * 1024];   // [N][1024]: fs2 | fd2
__device__ __align__(16) float g_h2[(size_t)NNODES * 128];    // layer-2 output [N,128]
// bf16 two-term splits of the GEMM A operand (x for layer1, h1 for layer2)
__device__ __align__(16) __nv_bfloat16 g_ahi[(size_t)NNODES * 128];
__device__ __align__(16) __nv_bfloat16 g_alo[(size_t)NNODES * 128];
// W^T splits: [2*Mh][K], max 65536 elements
__device__ __align__(16) __nv_bfloat16 g_wthi[65536];
__device__ __align__(16) __nv_bfloat16 g_wtlo[65536];
__device__ int g_deg[NNODES];
__device__ int g_off[NNODES + 1];
__device__ int g_cur[NNODES];
__device__ int g_csr[NEDGES];
__device__ int g_bsum[64];

// ---------------- PTX helpers (baseline PTX only: no tcgen05) ----------------
__device__ __forceinline__ uint32_t smem_u32(const void* p) {
    uint32_t a;
    asm("{ .reg .u64 t; cvta.to.shared.u64 t, %1; cvt.u32.u64 %0, t; }"
        : "=r"(a) : "l"(p));
    return a;
}

#define CP16(dst, src, nbytes) \
    asm volatile("cp.async.ca.shared.global [%0], [%1], 16, %2;" \
                 :: "r"(dst), "l"(src), "r"(nbytes) : "memory")
#define CP_COMMIT() asm volatile("cp.async.commit_group;" ::: "memory")
#define CP_WAIT0()  asm volatile("cp.async.wait_group 0;" ::: "memory")
#define CP_WAIT1()  asm volatile("cp.async.wait_group 1;" ::: "memory")

// D(f32) += A(bf16) @ B(bf16): m16n8k16, A row-major, B col-major
__device__ __forceinline__ void mma_bf16(float* d, const uint32_t* a, const uint32_t* b) {
    asm volatile(
        "mma.sync.aligned.m16n8k16.row.col.f32.bf16.bf16.f32 "
        "{%0,%1,%2,%3}, {%4,%5,%6,%7}, {%8,%9}, {%0,%1,%2,%3};"
        : "+f"(d[0]), "+f"(d[1]), "+f"(d[2]), "+f"(d[3])
        : "r"(a[0]), "r"(a[1]), "r"(a[2]), "r"(a[3]), "r"(b[0]), "r"(b[1]));
}

__device__ __forceinline__ float lrelu(float t) { return (t > 0.f) ? t : 0.2f * t; }

// ---------------- CSR construction ----------------
__global__ void k_zero_deg() {
    int i = blockIdx.x * blockDim.x + threadIdx.x;
    if (i < NNODES) g_deg[i] = 0;
}

__global__ void k_count(const int* __restrict__ dst) {
    for (int e = blockIdx.x * blockDim.x + threadIdx.x; e < NEDGES;
         e += gridDim.x * blockDim.x)
        atomicAdd(&g_deg[dst[e]], 1);
}

__global__ void k_scan1() {
    __shared__ int sh[1024];
    int tid = threadIdx.x;
    int i = blockIdx.x * 1024 + tid;
    int v = (i < NNODES) ? g_deg[i] : 0;
    sh[tid] = v;
    __syncthreads();
#pragma unroll
    for (int o = 1; o < 1024; o <<= 1) {
        int t = (tid >= o) ? sh[tid - o] : 0;
        __syncthreads();
        sh[tid] += t;
        __syncthreads();
    }
    if (i < NNODES) g_off[i] = sh[tid] - v;
    if (tid == 1023) g_bsum[blockIdx.x] = sh[1023];
}

__global__ void k_scan2() {
    __shared__ int sh[64];
    int tid = threadIdx.x;
    int v = (tid < 49) ? g_bsum[tid] : 0;
    sh[tid] = v;
    __syncthreads();
#pragma unroll
    for (int o = 1; o < 64; o <<= 1) {
        int t = (tid >= o) ? sh[tid - o] : 0;
        __syncthreads();
        sh[tid] += t;
        __syncthreads();
    }
    if (tid < 49) g_bsum[tid] = sh[tid] - v;
    if (tid == 0) g_off[NNODES] = NEDGES;
}

__global__ void k_scan3() {
    int i = blockIdx.x * blockDim.x + threadIdx.x;
    if (i < NNODES) {
        int o = g_off[i] + g_bsum[i >> 10];
        g_off[i] = o;
        g_cur[i] = o;
    }
}

__global__ void k_scatter(const int* __restrict__ src, const int* __restrict__ dst) {
    for (int e = blockIdx.x * blockDim.x + threadIdx.x; e < NEDGES;
         e += gridDim.x * blockDim.x) {
        int pos = atomicAdd(&g_cur[dst[e]], 1);
        g_csr[pos] = src[e];
    }
}

// ---------------- bf16 hi/lo split of x ----------------
__global__ void k_split_x(const float* __restrict__ x) {
    for (int i = blockIdx.x * blockDim.x + threadIdx.x; i < NNODES * 128;
         i += gridDim.x * blockDim.x) {
        float v = x[i];
        __nv_bfloat16 h = __float2bfloat16(v);
        g_ahi[i] = h;
        g_alo[i] = __float2bfloat16(v - __bfloat162float(h));
    }
}

// ---------------- W^T + bf16 split: g_wt*[c][k] = split(W[k][c]) ----------
__global__ void k_prepw(const float* __restrict__ Wl, const float* __restrict__ Wr,
                        int Mh, int K) {
    int idx = blockIdx.x * blockDim.x + threadIdx.x;
    int tot = 2 * Mh * K;
    if (idx >= tot) return;
    int c = idx % (2 * Mh);
    int k = idx / (2 * Mh);
    float v = (c < Mh) ? Wl[(size_t)k * Mh + c] : Wr[(size_t)k * Mh + (c - Mh)];
    __nv_bfloat16 h = __float2bfloat16(v);
    g_wthi[(size_t)c * K + k] = h;
    g_wtlo[(size_t)c * K + k] = __float2bfloat16(v - __bfloat162float(h));
}

// ---------------- bf16x3 mma.sync GEMM ----------------
// out[n, 2Mh] = A @ W^T + bias via Ah·Bh + Ah·Bl + Al·Bh (f32 accumulate).
// Block tile 128 rows x 64 cols, 8 warps (4x2), warp tile 32x32.
// BK=32, cp.async double buffer. SMEM rows padded to 80B (conflict-free lds).
template <int K, int Mh, int LAYER>
__launch_bounds__(256, 2)
__global__ void gemm_bf16(const float* __restrict__ bl, const float* __restrict__ br) {
    constexpr int NT = K / 32;
    constexpr int T_AH = 0, T_AL = 10240, T_BH = 20480, T_BL = 25600, STG = 30720;
    float* __restrict__ out = (LAYER == 1) ? g_f1 : g_f2;

    extern __shared__ __align__(16) char sm[];
    const uint32_t smb = smem_u32(sm);

    const int tid = threadIdx.x, wid = tid >> 5, lane = tid & 31;
    const int g = lane >> 2, t = lane & 3;
    const int wm = wid & 3, wn = wid >> 2;           // 4 x 2 warp grid
    const int r0 = blockIdx.x * 128;
    const int c0 = blockIdx.y * 64;

    const int aRowA = tid >> 2, aQ = tid & 3;        // A: 2 uint4/thread/tile
    const int aRowB = (tid + 256) >> 2;
    const int bRow = tid >> 2, bQ = tid & 3;         // B: 1 uint4/thread/tile

    auto fill = [&](int buf, int kb) {
        uint32_t bo = smb + buf * STG;
        {
            int gr = r0 + aRowA;
            int grc = (gr < NNODES) ? gr : (NNODES - 1);
            int n = (gr < NNODES) ? 16 : 0;
            uint32_t d = bo + aRowA * 80 + aQ * 16;
            const char* s1 = (const char*)g_ahi + ((size_t)grc * K + kb + aQ * 8) * 2;
            const char* s2 = (const char*)g_alo + ((size_t)grc * K + kb + aQ * 8) * 2;
            CP16(d + T_AH, s1, n);
            CP16(d + T_AL, s2, n);
        }
        {
            int gr = r0 + aRowB;
            int grc = (gr < NNODES) ? gr : (NNODES - 1);
            int n = (gr < NNODES) ? 16 : 0;
            uint32_t d = bo + aRowB * 80 + aQ * 16;
            const char* s1 = (const char*)g_ahi + ((size_t)grc * K + kb + aQ * 8) * 2;
            const char* s2 = (const char*)g_alo + ((size_t)grc * K + kb + aQ * 8) * 2;
            CP16(d + T_AH, s1, n);
            CP16(d + T_AL, s2, n);
        }
        {
            uint32_t d = bo + bRow * 80 + bQ * 16;
            const char* s1 = (const char*)g_wthi + ((size_t)(c0 + bRow) * K + kb + bQ * 8) * 2;
            const char* s2 = (const char*)g_wtlo + ((size_t)(c0 + bRow) * K + kb + bQ * 8) * 2;
            CP16(d + T_BH, s1, 16);
            CP16(d + T_BL, s2, 16);
        }
    };

    float acc[2][4][4] = {};

    fill(0, 0);
    CP_COMMIT();

    for (int s = 0; s < NT; s++) {
        if (s + 1 < NT) {
            fill((s + 1) & 1, (s + 1) * 32);
            CP_COMMIT();
            CP_WAIT1();
        } else {
            CP_WAIT0();
        }
        __syncthreads();
        const char* bo = sm + (s & 1) * STG;
#pragma unroll
        for (int ks = 0; ks < 2; ks++) {
            const int ksb = ks * 32;   // 16 bf16 = 32 bytes
            uint32_t ah[2][4], al[2][4];
#pragma unroll
            for (int mi = 0; mi < 2; mi++) {
                const char* p = bo + (wm * 32 + mi * 16 + g) * 80 + ksb + t * 4;
                ah[mi][0] = *(const uint32_t*)(p + T_AH);
                ah[mi][1] = *(const uint32_t*)(p + T_AH + 640);
                ah[mi][2] = *(const uint32_t*)(p + T_AH + 16);
                ah[mi][3] = *(const uint32_t*)(p + T_AH + 656);
                al[mi][0] = *(const uint32_t*)(p + T_AL);
                al[mi][1] = *(const uint32_t*)(p + T_AL + 640);
                al[mi][2] = *(const uint32_t*)(p + T_AL + 16);
                al[mi][3] = *(const uint32_t*)(p + T_AL + 656);
            }
            uint32_t bh[4][2], blr[4][2];
#pragma unroll
            for (int ni = 0; ni < 4; ni++) {
                const char* p = bo + (wn * 32 + ni * 8 + g) * 80 + ksb + t * 4;
                bh[ni][0] = *(const uint32_t*)(p + T_BH);
                bh[ni][1] = *(const uint32_t*)(p + T_BH + 16);
                blr[ni][0] = *(const uint32_t*)(p + T_BL);
                blr[ni][1] = *(const uint32_t*)(p + T_BL + 16);
            }
#pragma unroll
            for (int mi = 0; mi < 2; mi++)
#pragma unroll
                for (int ni = 0; ni < 4; ni++) {
                    mma_bf16(acc[mi][ni], ah[mi], bh[ni]);
                    mma_bf16(acc[mi][ni], ah[mi], blr[ni]);
                    mma_bf16(acc[mi][ni], al[mi], bh[ni]);
                }
        }
        __syncthreads();
    }

    const float* bb = (c0 < Mh) ? (bl + c0) : (br + (c0 - Mh));
    constexpr int M2 = 2 * Mh;
#pragma unroll
    for (int mi = 0; mi < 2; mi++) {
#pragma unroll
        for (int ni = 0; ni < 4; ni++) {
            int lc = wn * 32 + ni * 8 + 2 * t;
            float2 bv = *(const float2*)&bb[lc];
            int row0 = r0 + wm * 32 + mi * 16 + g;
            int col = c0 + lc;
            if (row0 < NNODES) {
                float2 o;
                o.x = acc[mi][ni][0] + bv.x;
                o.y = acc[mi][ni][1] + bv.y;
                *(float2*)&out[(size_t)row0 * M2 + col] = o;
            }
            int row1 = row0 + 8;
            if (row1 < NNODES) {
                float2 o;
                o.x = acc[mi][ni][2] + bv.x;
                o.y = acc[mi][ni][3] + bv.y;
                *(float2*)&out[(size_t)row1 * M2 + col] = o;
            }
        }
    }
}

// ---------------- GATv2 aggregation, layer 1 (D=64): warp-per-node ---------
// Warp layout: lane = h*8 + j (4 heads x 8 lanes), each lane holds 8 dims.
// 3-shfl in-head reduce; cross-head max via shfl xor 8,16. Prefetched edges.
// Output written directly as bf16 hi/lo splits (layer-2 GEMM input).
__launch_bounds__(256)
__global__ void gat_agg64(const float* __restrict__ attn) {
    const int w = threadIdx.x >> 5, lane = threadIdx.x & 31;
    const int v = blockIdx.x * 8 + w;               // 50000 % 8 == 0 via grid
    const int h = lane >> 3, j = lane & 7;

    const float* base = g_f1;
    const float* pfd = base + (size_t)v * 512 + 256 + h * 64 + j * 8;
    float4 fd0 = *(const float4*)pfd;
    float4 fd1 = *(const float4*)(pfd + 4);
    const float* pa = attn + h * 64 + j * 8;
    float4 a0 = *(const float4*)pa;
    float4 a1 = *(const float4*)(pa + 4);

    const int e0 = g_off[v], e1 = g_off[v + 1];

    float m = __int_as_float(0xff800000u);
    float s = 0.f;
    float4 ac0 = {0.f, 0.f, 0.f, 0.f}, ac1 = {0.f, 0.f, 0.f, 0.f};

    float4 f0, f1;
    if (e0 < e1) {
        const float* p = base + (size_t)g_csr[e0] * 512 + h * 64 + j * 8;
        f0 = *(const float4*)p;
        f1 = *(const float4*)(p + 4);
    }
    for (int e = e0; e < e1; e++) {
        float4 c0 = f0, c1 = f1;
        if (e + 1 < e1) {   // prefetch next edge
            const float* p = base + (size_t)g_csr[e + 1] * 512 + h * 64 + j * 8;
            f0 = *(const float4*)p;
            f1 = *(const float4*)(p + 4);
        }
        float pd;
        pd = a0.x * lrelu(c0.x + fd0.x);
        pd = fmaf(a0.y, lrelu(c0.y + fd0.y), pd);
        pd = fmaf(a0.z, lrelu(c0.z + fd0.z), pd);
        pd = fmaf(a0.w, lrelu(c0.w + fd0.w), pd);
        pd = fmaf(a1.x, lrelu(c1.x + fd1.x), pd);
        pd = fmaf(a1.y, lrelu(c1.y + fd1.y), pd);
        pd = fmaf(a1.z, lrelu(c1.z + fd1.z), pd);
        pd = fmaf(a1.w, lrelu(c1.w + fd1.w), pd);
        pd += __shfl_xor_sync(0xffffffffu, pd, 1);
        pd += __shfl_xor_sync(0xffffffffu, pd, 2);
        pd += __shfl_xor_sync(0xffffffffu, pd, 4);
        if (pd > m) {
            float cc = __expf(m - pd);
            s *= cc;
            ac0.x *= cc; ac0.y *= cc; ac0.z *= cc; ac0.w *= cc;
            ac1.x *= cc; ac1.y *= cc; ac1.z *= cc; ac1.w *= cc;
            m = pd;
        }
        float wt = __expf(pd - m);
        s += wt;
        ac0.x = fmaf(wt, c0.x, ac0.x); ac0.y = fmaf(wt, c0.y, ac0.y);
        ac0.z = fmaf(wt, c0.z, ac0.z); ac0.w = fmaf(wt, c0.w, ac0.w);
        ac1.x = fmaf(wt, c1.x, ac1.x); ac1.y = fmaf(wt, c1.y, ac1.y);
        ac1.z = fmaf(wt, c1.z, ac1.z); ac1.w = fmaf(wt, c1.w, ac1.w);
    }

    float inv = (e1 > e0) ? 1.f / s : 0.f;
    float r[8] = {ac0.x * inv, ac0.y * inv, ac0.z * inv, ac0.w * inv,
                  ac1.x * inv, ac1.y * inv, ac1.z * inv, ac1.w * inv};
    // max over heads: lanes h*8+j for h=0..3 hold the same dim slots
#pragma unroll
    for (int k = 0; k < 8; k++) {
        r[k] = fmaxf(r[k], __shfl_xor_sync(0xffffffffu, r[k], 8));
        r[k] = fmaxf(r[k], __shfl_xor_sync(0xffffffffu, r[k], 16));
    }
    if (h == 0) {   // lanes 0..7 write dims j*8 .. j*8+7 as bf16 hi/lo
        __nv_bfloat162 hi4[4], lo4[4];
#pragma unroll
        for (int k = 0; k < 4; k++) {
            __nv_bfloat16 hA = __float2bfloat16(r[2 * k]);
            __nv_bfloat16 hB = __float2bfloat16(r[2 * k + 1]);
            hi4[k] = __nv_bfloat162(hA, hB);
            lo4[k] = __nv_bfloat162(
                __float2bfloat16(r[2 * k] - __bfloat162float(hA)),
                __float2bfloat16(r[2 * k + 1] - __bfloat162float(hB)));
        }
        *(uint4*)&g_ahi[(size_t)v * 64 + j * 8] = *(uint4*)hi4;
        *(uint4*)&g_alo[(size_t)v * 64 + j * 8] = *(uint4*)lo4;
    }
}

// ---------------- GATv2 aggregation, layer 2 (D=128): warp-per-head --------
// One block (128 thr) per node, warp per head, lane holds 4 dims. Prefetched.
__launch_bounds__(128)
__global__ void gat_agg128(const float* __restrict__ attn) {
    const int v = blockIdx.x;
    const int h = threadIdx.x >> 5, lane = threadIdx.x & 31;

    __shared__ float sh[512];

    const float* base = g_f2;
    const int e0 = g_off[v], e1 = g_off[v + 1];

    float4 fd = *(const float4*)(base + (size_t)v * 1024 + 512 + h * 128 + lane * 4);
    float4 ar = *(const float4*)(attn + h * 128 + lane * 4);

    float m = __int_as_float(0xff800000u);
    float s = 0.f;
    float4 ac = {0.f, 0.f, 0.f, 0.f};

    float4 fv;
    if (e0 < e1)
        fv = *(const float4*)(base + (size_t)g_csr[e0] * 1024 + h * 128 + lane * 4);
    for (int e = e0; e < e1; e++) {
        float4 c = fv;
        if (e + 1 < e1)
            fv = *(const float4*)(base + (size_t)g_csr[e + 1] * 1024 + h * 128 + lane * 4);
        float pd;
        pd = ar.x * lrelu(c.x + fd.x);
        pd = fmaf(ar.y, lrelu(c.y + fd.y), pd);
        pd = fmaf(ar.z, lrelu(c.z + fd.z), pd);
        pd = fmaf(ar.w, lrelu(c.w + fd.w), pd);
#pragma unroll
        for (int o = 16; o; o >>= 1) pd += __shfl_xor_sync(0xffffffffu, pd, o);
        if (pd > m) {
            float cc = __expf(m - pd);
            s *= cc;
            ac.x *= cc; ac.y *= cc; ac.z *= cc; ac.w *= cc;
            m = pd;
        }
        float wt = __expf(pd - m);
        s += wt;
        ac.x = fmaf(wt, c.x, ac.x); ac.y = fmaf(wt, c.y, ac.y);
        ac.z = fmaf(wt, c.z, ac.z); ac.w = fmaf(wt, c.w, ac.w);
    }

    float inv = (e1 > e0) ? 1.f / s : 0.f;
    float4 o4 = {ac.x * inv, ac.y * inv, ac.z * inv, ac.w * inv};
    *(float4*)&sh[h * 128 + lane * 4] = o4;
    __syncthreads();

    int d = threadIdx.x;
    float mx = fmaxf(fmaxf(sh[d], sh[128 + d]), fmaxf(sh[256 + d], sh[384 + d]));
    g_h2[(size_t)v * 128 + d] = mx;
}

// ---------------- global attention pooling (512 threads / graph) -----------
__launch_bounds__(512)
__global__ void gate_pool(const float* __restrict__ gw, const float* __restrict__ gb,
                          float* __restrict__ out) {
    int g = blockIdx.x;
    int n0 = g * NPG;
    __shared__ __align__(16) float sgw[128];
    __shared__ float sg[NPG];
    __shared__ float red[16];
    __shared__ float partial[4][128];
    __shared__ float s_val;

    int tid = threadIdx.x, warp = tid >> 5, lane = tid & 31;
    if (tid < 128) sgw[tid] = gw[tid];
    __syncthreads();

    float gbv = gb[0];
    for (int n = warp; n < NPG; n += 16) {
        const float4 hv = *(const float4*)(g_h2 + (size_t)(n0 + n) * 128 + lane * 4);
        const float4 wv = *(const float4*)(sgw + lane * 4);
        float p = hv.x * wv.x + hv.y * wv.y + hv.z * wv.z + hv.w * wv.w;
#pragma unroll
        for (int o = 16; o; o >>= 1) p += __shfl_xor_sync(0xffffffffu, p, o);
        if (lane == 0) sg[n] = p + gbv;
    }
    __syncthreads();

    float mx = __int_as_float(0xff800000u);
    for (int n = tid; n < NPG; n += 512) mx = fmaxf(mx, sg[n]);
#pragma unroll
    for (int o = 16; o; o >>= 1) mx = fmaxf(mx, __shfl_xor_sync(0xffffffffu, mx, o));
    if (lane == 0) red[warp] = mx;
    __syncthreads();
    if (tid == 0) {
        float t = red[0];
        for (int i = 1; i < 16; i++) t = fmaxf(t, red[i]);
        s_val = t;
    }
    __syncthreads();
    float gmax = s_val;
    __syncthreads();

    float ps = 0.f;
    for (int n = tid; n < NPG; n += 512) {
        float e = __expf(sg[n] - gmax);
        sg[n] = e;
        ps += e;
    }
#pragma unroll
    for (int o = 16; o; o >>= 1) ps += __shfl_xor_sync(0xffffffffu, ps, o);
    if (lane == 0) red[warp] = ps;
    __syncthreads();
    if (tid == 0) {
        float t = 0.f;
        for (int i = 0; i < 16; i++) t += red[i];
        s_val = 1.f / t;
    }
    __syncthreads();
    float sinv = s_val;

    int grp = tid >> 7;
    int d = tid & 127;
    float a0 = 0.f, a1 = 0.f;
    int nA = grp * 250, nB = nA + 250;
    for (int n = nA; n < nB; n += 2) {
        a0 = fmaf(sg[n + 0], g_h2[(size_t)(n0 + n + 0) * 128 + d], a0);
        a1 = fmaf(sg[n + 1], g_h2[(size_t)(n0 + n + 1) * 128 + d], a1);
    }
    partial[grp][d] = a0 + a1;
    __syncthreads();
    if (tid < 128) {
        out[g * 128 + tid] =
            (partial[0][tid] + partial[1][tid] + partial[2][tid] + partial[3][tid]) * sinv;
    }
}

// ---------------- launch ----------------
extern "C" void kernel_launch(void* const* d_in, const int* in_sizes, int n_in,
                              void* d_out, int out_size) {
    (void)in_sizes; (void)n_in; (void)out_size;
    const float* x     = (const float*)d_in[0];
    const int*   esrc  = (const int*)d_in[1];
    const int*   edst  = (const int*)d_in[2];
    const float* Wl1   = (const float*)d_in[4];
    const float* bl1   = (const float*)d_in[5];
    const float* Wr1   = (const float*)d_in[6];
    const float* br1   = (const float*)d_in[7];
    const float* attn1 = (const float*)d_in[8];
    const float* Wl2   = (const float*)d_in[9];
    const float* bl2   = (const float*)d_in[10];
    const float* Wr2   = (const float*)d_in[11];
    const float* br2   = (const float*)d_in[12];
    const float* attn2 = (const float*)d_in[13];
    const float* gw    = (const float*)d_in[14];
    const float* gb    = (const float*)d_in[15];
    float* out = (float*)d_out;

    const int SMEM_GEMM = 61440;   // 2 stages x 30720
    cudaFuncSetAttribute(gemm_bf16<128, 256, 1>,
                         cudaFuncAttributeMaxDynamicSharedMemorySize, SMEM_GEMM);
    cudaFuncSetAttribute(gemm_bf16<64, 512, 2>,
                         cudaFuncAttributeMaxDynamicSharedMemorySize, SMEM_GEMM);

    const int RB = (NNODES + 127) / 128;   // 391 row blocks

    // Order chosen so gemm1 is the 4th launch (ncu profiles launch index 3),
    // while respecting deps (gemm1 needs split_x+prepw1; CSR before agg).
    k_split_x<<<512, 256>>>(x);                                       // 0
    k_prepw<<<(2 * 256 * 128 + 255) / 256, 256>>>(Wl1, Wr1, 256, 128); // 1
    k_zero_deg<<<(NNODES + 255) / 256, 256>>>();                      // 2
    gemm_bf16<128, 256, 1><<<dim3(RB, 8), 256, SMEM_GEMM>>>(bl1, br1); // 3 <- profiled
    k_count<<<512, 256>>>(edst);
    k_scan1<<<49, 1024>>>();
    k_scan2<<<1, 64>>>();
    k_scan3<<<(NNODES + 255) / 256, 256>>>();
    k_scatter<<<512, 256>>>(esrc, edst);

    gat_agg64<<<NNODES / 8, 256>>>(attn1);   // writes bf16 splits for layer 2

    k_prepw<<<(2 * 512 * 64 + 255) / 256, 256>>>(Wl2, Wr2, 512, 64);
    gemm_bf16<64, 512, 2><<<dim3(RB, 16), 256, SMEM_GEMM>>>(bl2, br2);
    gat_agg128<<<NNODES, 128>>>(attn2);

    gate_pool<<<NGRAPH, 512>>>(gw, gb, out);
}